// round 15
// baseline (speedup 1.0000x reference)
#include <cuda_runtime.h>
#include <cstdint>

#define BB   64
#define NN   256
#define TT   10240
#define VV   100
#define DIM  128
#define HH   9
#define HD   72
#define RR   8
#define FFD  512
#define BN   (BB*NN)
#define JC   32
#define UTS  40

// attention dyn smem layout (floats)
#define QS 76
#define KS 76
#define VS 76
#define ES 36
#define OS 76
#define oQ  0
#define oK  (16*QS)
#define oV  (oK + JC*KS)
#define oE  (oV + JC*VS)
#define oUT (oE + 9*16*ES)
#define oO  (oUT + 16*UTS*2)
#define ATTN_DYN ((oO + 16*OS)*4)

// ---------------- scratch ----------------
__device__ float g_h[BN*DIM];
__device__ float g_hn[BN*DIM];
__device__ float g_q[BN*HD];
__device__ float g_k[BN*HD];
__device__ float g_v[BN*HD];
__device__ float g_coors[BN*3];
__device__ int   g_starts[BB];
__device__ int   g_cnt[BB];
__device__ float g_qt[VV*HD], g_kt[VV*HD], g_vt[VV*HD];

// 2^x; exact 0 below -120
__device__ __forceinline__ float exp2p(float x) {
    if (x < -120.0f) return 0.0f;
    float n = floorf(x);
    float t = x - n;
    float p = 1.0f + t*(0.69314718f + t*(0.24022651f + t*(0.05550411f +
              t*(0.00961812f + t*(0.00133335f + t*1.54035e-4f)))));
    return __int_as_float(((int)n + 127) << 23) * p;
}

__device__ __forceinline__ float f2tf_f(float x) {
    uint32_t r; asm("cvt.rna.tf32.f32 %0, %1;" : "=r"(r) : "f"(x));
    return __uint_as_float(r);
}
__device__ __forceinline__ uint32_t f2tf_u(float x) {
    uint32_t r; asm("cvt.rna.tf32.f32 %0, %1;" : "=r"(r) : "f"(x));
    return r;
}
__device__ __forceinline__ float4 f2tf_4(float4 v) {
    return make_float4(f2tf_f(v.x), f2tf_f(v.y), f2tf_f(v.z), f2tf_f(v.w));
}
__device__ __forceinline__ void mma8(float* c, uint32_t a0, uint32_t a1, uint32_t a2,
                                     uint32_t a3, uint32_t b0, uint32_t b1) {
    asm volatile("mma.sync.aligned.m16n8k8.row.col.f32.tf32.tf32.f32 "
                 "{%0,%1,%2,%3},{%4,%5,%6,%7},{%8,%9},{%0,%1,%2,%3};"
                 : "+f"(c[0]), "+f"(c[1]), "+f"(c[2]), "+f"(c[3])
                 : "r"(a0), "r"(a1), "r"(a2), "r"(a3), "r"(b0), "r"(b1));
}

// ---------------- K1: per-vocab LN1 + QKV tables (+starts in block 0) --------
__global__ void k_vocab(const float* __restrict__ embed, const float* __restrict__ Wq,
                        const float* __restrict__ Wk, const float* __restrict__ Wv,
                        const float* __restrict__ g1, const float* __restrict__ b1,
                        const int* __restrict__ batch) {
    int r = blockIdx.x, t = threadIdx.x;
    if (r == 0 && t < BB) {
        int b = t;
        int lo = 0, hi = TT;
        while (lo < hi) { int mid = (lo + hi) >> 1; if (batch[mid] < b) lo = mid + 1; else hi = mid; }
        g_starts[b] = lo;
        int lo2 = 0, hi2 = TT, b1i = b + 1;
        while (lo2 < hi2) { int mid = (lo2 + hi2) >> 1; if (batch[mid] < b1i) lo2 = mid + 1; else hi2 = mid; }
        int c = lo2 - lo;
        g_cnt[b] = c > NN ? NN : c;
    }
    __shared__ float hn[DIM];
    __shared__ float2 red[4];
    float v = embed[r*DIM + t];
    float s = v, s2 = v*v;
    #pragma unroll
    for (int o = 16; o; o >>= 1) {
        s  += __shfl_xor_sync(0xffffffffu, s,  o);
        s2 += __shfl_xor_sync(0xffffffffu, s2, o);
    }
    if ((t & 31) == 0) red[t >> 5] = make_float2(s, s2);
    __syncthreads();
    float S  = red[0].x + red[1].x + red[2].x + red[3].x;
    float S2 = red[0].y + red[1].y + red[2].y + red[3].y;
    float mu  = S * (1.0f/DIM);
    float var = S2 * (1.0f/DIM) - mu*mu;
    hn[t] = (v - mu) * rsqrtf(var + 1e-5f) * g1[t] + b1[t];
    __syncthreads();
    for (int c = t; c < 3*HD; c += DIM) {
        const float* W = (c < HD) ? Wq : ((c < 2*HD) ? Wk : Wv);
        int col = c % HD;
        float a = 0.0f;
        #pragma unroll 8
        for (int d = 0; d < DIM; d++) a += hn[d] * W[d*HD + col];
        float* Tb = (c < HD) ? g_qt : ((c < 2*HD) ? g_kt : g_vt);
        Tb[r*HD + col] = a;
    }
}

// ---------------- K2: scatter (float4, 96 threads) ----------------
__global__ void k_scatter(const int* __restrict__ x, const float* __restrict__ pos,
                          const int* __restrict__ batch, const float* __restrict__ embed) {
    int t = blockIdx.x, d = threadIdx.x;
    int b = batch[t];
    int idx = t - g_starts[b];
    if (idx >= NN) return;
    int row = b*NN + idx;
    int xv = x[t];
    if (d < 32) {
        ((float4*)g_h)[(size_t)row*32 + d] = ((const float4*)embed)[(size_t)xv*32 + d];
    } else if (d < 50) {
        ((float4*)g_q)[(size_t)row*18 + (d-32)] = ((const float4*)g_qt)[xv*18 + (d-32)];
    } else if (d < 68) {
        ((float4*)g_k)[(size_t)row*18 + (d-50)] = ((const float4*)g_kt)[xv*18 + (d-50)];
    } else if (d < 86) {
        ((float4*)g_v)[(size_t)row*18 + (d-68)] = ((const float4*)g_vt)[xv*18 + (d-68)];
    } else if (d < 89) {
        g_coors[row*3 + (d-86)] = pos[t*3 + (d-86)];
    }
}

// ---------------- K3: attention + fused LN2 (unchanged) ----------------
__global__ __launch_bounds__(288, 3) void k_attn(const float* __restrict__ Wrbf,
                                                 const float* __restrict__ Wo,
                                                 const float* __restrict__ ln2g,
                                                 const float* __restrict__ ln2b) {
    int b = blockIdx.y, i0 = blockIdx.x*16, tid = threadIdx.x;
    int cnt = g_cnt[b];
    if (i0 >= cnt) return;
    int nch = (cnt + JC - 1) / JC;
    int w = tid >> 5, lane = tid & 31, g = lane >> 2, tg = lane & 3;
    extern __shared__ float dyn[];
    float*  sQ  = dyn + oQ;
    float*  sK  = dyn + oK;
    float*  sV  = dyn + oV;
    float*  sE  = dyn + oE;
    float2* sUT = (float2*)(dyn + oUT);
    float*  sO  = dyn + oO;
    __shared__ __align__(16) float sW4[HH*8];
    __shared__ float sCI[48];

    {
        const float4* src = (const float4*)(g_q + (size_t)(b*NN + i0)*HD);
        for (int t4 = tid; t4 < 16*18; t4 += 288) {
            float4 vq = src[t4];
            float* dst = sQ + (t4/18)*QS + (t4%18)*4;
            dst[0]=f2tf_f(vq.x); dst[1]=f2tf_f(vq.y); dst[2]=f2tf_f(vq.z); dst[3]=f2tf_f(vq.w);
        }
    }
    if (tid < HH*8) {
        int h = tid >> 3, r = tid & 7;
        float cr = 1.14285714f * (float)r;
        sW4[h*8 + r] = Wrbf[r*HH + h] * expf(-0.5f*cr*cr);
    }
    if (tid < 48) sCI[tid] = g_coors[(b*NN + i0)*3 + tid];
    __syncthreads();

    uint32_t aq0 = __float_as_uint(sQ[g*QS + w*8 + tg]);
    uint32_t aq1 = __float_as_uint(sQ[(g+8)*QS + w*8 + tg]);
    uint32_t aq2 = __float_as_uint(sQ[g*QS + w*8 + tg + 4]);
    uint32_t aq3 = __float_as_uint(sQ[(g+8)*QS + w*8 + tg + 4]);

    float oc[4] = {0.f,0.f,0.f,0.f};
    float rs0 = 0.f, rs1 = 0.f;
    float* Eh = sE + w*16*ES;

    for (int c = 0; c < nch; c++) {
        __syncthreads();
        {
            const float4* ksrc = (const float4*)(g_k + (size_t)(b*NN + c*JC)*HD);
            const float4* vsrc = (const float4*)(g_v + (size_t)(b*NN + c*JC)*HD);
            for (int t4 = tid; t4 < JC*18; t4 += 288) {
                int r = t4/18, c4 = t4%18;
                float4 kv = ksrc[t4];
                float* kd = sK + r*KS + c4*4;
                kd[0]=f2tf_f(kv.x); kd[1]=f2tf_f(kv.y); kd[2]=f2tf_f(kv.z); kd[3]=f2tf_f(kv.w);
                float4 vv = vsrc[t4];
                float* vd = sV + r*VS + c4*4;
                vd[0]=f2tf_f(vv.x); vd[1]=f2tf_f(vv.y); vd[2]=f2tf_f(vv.z); vd[3]=f2tf_f(vv.w);
            }
        }
        for (int p = tid; p < 16*JC; p += 288) {
            int i = p >> 5, j = p & 31;
            int jj = c*JC + j;
            float2 ut;
            if (i0 + i < cnt && jj < cnt) {
                int rowj = b*NN + jj;
                float dx = sCI[i*3]  - g_coors[rowj*3];
                float dy = sCI[i*3+1]- g_coors[rowj*3+1];
                float dz = sCI[i*3+2]- g_coors[rowj*3+2];
                float ss = dx*dx + dy*dy + dz*dz + 1e-8f;
                if (ss < 200.0f) {
                    float dist = ss * rsqrtf(ss);
                    ut.x = 1.44269504f * exp2p(-0.72134752f * ss);
                    ut.y = exp2p(1.64879462f * dist);
                } else { ut.x = 0.0f; ut.y = 1.0f; }
            } else { ut.x = 0.0f; ut.y = -1.0f; }
            sUT[i*UTS + j] = ut;
        }
        __syncthreads();

        float4 w0 = *(const float4*)(sW4 + w*8);
        float4 w1 = *(const float4*)(sW4 + w*8 + 4);

        #pragma unroll
        for (int nt = 0; nt < 4; nt++) {
            float cf[4] = {0.f,0.f,0.f,0.f};
            int kro = (nt*8 + g)*KS + w*8;
            uint32_t b0 = __float_as_uint(sK[kro + tg]);
            uint32_t b1 = __float_as_uint(sK[kro + tg + 4]);
            mma8(cf, aq0, aq1, aq2, aq3, b0, b1);
            int j0 = nt*8 + 2*tg;
            #pragma unroll
            for (int q = 0; q < 4; q++) {
                int ii = (q >= 2) ? (g+8) : g;
                int jj2 = j0 + (q & 1);
                float2 ut = sUT[ii*UTS + jj2];
                float e;
                if (ut.y < 0.0f) e = 0.0f;
                else {
                    float tt = ut.y;
                    float acc = w1.w;
                    acc = acc*tt + w1.z;  acc = acc*tt + w1.y;  acc = acc*tt + w1.x;
                    acc = acc*tt + w0.w;  acc = acc*tt + w0.z;  acc = acc*tt + w0.y;
                    acc = acc*tt + w0.x;
                    e = exp2p(cf[q]*0.51012853f + acc*ut.x);
                }
                if (q < 2) rs0 += e; else rs1 += e;
                Eh[ii*ES + jj2] = f2tf_f(e);
            }
        }

        #pragma unroll
        for (int ks = 0; ks < 4; ks++) {
            uint32_t a0 = __float_as_uint(Eh[g*ES + ks*8 + tg]);
            uint32_t a1 = __float_as_uint(Eh[(g+8)*ES + ks*8 + tg]);
            uint32_t a2 = __float_as_uint(Eh[g*ES + ks*8 + tg + 4]);
            uint32_t a3 = __float_as_uint(Eh[(g+8)*ES + ks*8 + tg + 4]);
            uint32_t b0 = __float_as_uint(sV[(ks*8 + tg)*VS + w*8 + g]);
            uint32_t b1 = __float_as_uint(sV[(ks*8 + tg + 4)*VS + w*8 + g]);
            mma8(oc, a0, a1, a2, a3, b0, b1);
        }
    }

    rs0 += __shfl_xor_sync(0xffffffffu, rs0, 1);
    rs0 += __shfl_xor_sync(0xffffffffu, rs0, 2);
    rs1 += __shfl_xor_sync(0xffffffffu, rs1, 1);
    rs1 += __shfl_xor_sync(0xffffffffu, rs1, 2);
    float inv0 = (rs0 > 0.0f) ? 1.0f/rs0 : 0.0f;
    float inv1 = (rs1 > 0.0f) ? 1.0f/rs1 : 0.0f;
    sO[g*OS + w*8 + 2*tg]       = oc[0]*inv0;
    sO[g*OS + w*8 + 2*tg + 1]   = oc[1]*inv0;
    sO[(g+8)*OS + w*8 + 2*tg]   = oc[2]*inv1;
    sO[(g+8)*OS + w*8 + 2*tg+1] = oc[3]*inv1;
    __syncthreads();

    if (w < 8) {
        int r0 = 2*w, r1 = 2*w + 1;
        size_t row0 = (size_t)(b*NN + i0 + r0), row1 = row0 + 1;
        const float4* Wo4 = (const float4*)Wo;
        float4 a0 = ((const float4*)g_h)[row0*32 + lane];
        float4 a1 = ((const float4*)g_h)[row1*32 + lane];
        #pragma unroll 8
        for (int cc = 0; cc < HD; cc++) {
            float4 wv = Wo4[cc*32 + lane];
            float s0 = sO[r0*OS + cc], s1 = sO[r1*OS + cc];
            a0.x += s0*wv.x; a0.y += s0*wv.y; a0.z += s0*wv.z; a0.w += s0*wv.w;
            a1.x += s1*wv.x; a1.y += s1*wv.y; a1.z += s1*wv.z; a1.w += s1*wv.w;
        }
        float s0 = a0.x+a0.y+a0.z+a0.w, q0 = a0.x*a0.x+a0.y*a0.y+a0.z*a0.z+a0.w*a0.w;
        float s1 = a1.x+a1.y+a1.z+a1.w, q1 = a1.x*a1.x+a1.y*a1.y+a1.z*a1.z+a1.w*a1.w;
        #pragma unroll
        for (int o = 16; o; o >>= 1) {
            s0 += __shfl_xor_sync(0xffffffffu, s0, o);
            q0 += __shfl_xor_sync(0xffffffffu, q0, o);
            s1 += __shfl_xor_sync(0xffffffffu, s1, o);
            q1 += __shfl_xor_sync(0xffffffffu, q1, o);
        }
        float mu0 = s0*(1.0f/DIM), var0 = q0*(1.0f/DIM) - mu0*mu0;
        float mu1 = s1*(1.0f/DIM), var1 = q1*(1.0f/DIM) - mu1*mu1;
        float ri0 = rsqrtf(var0 + 1e-5f), ri1 = rsqrtf(var1 + 1e-5f);
        float4 gv = ((const float4*)ln2g)[lane], bv = ((const float4*)ln2b)[lane];
        float4 h0, h1;
        h0.x = (a0.x-mu0)*ri0*gv.x + bv.x;  h0.y = (a0.y-mu0)*ri0*gv.y + bv.y;
        h0.z = (a0.z-mu0)*ri0*gv.z + bv.z;  h0.w = (a0.w-mu0)*ri0*gv.w + bv.w;
        h1.x = (a1.x-mu1)*ri1*gv.x + bv.x;  h1.y = (a1.y-mu1)*ri1*gv.y + bv.y;
        h1.z = (a1.z-mu1)*ri1*gv.z + bv.z;  h1.w = (a1.w-mu1)*ri1*gv.w + bv.w;
        ((float4*)g_h)[row0*32 + lane]  = a0;
        ((float4*)g_h)[row1*32 + lane]  = a1;
        ((float4*)g_hn)[row0*32 + lane] = h0;
        ((float4*)g_hn)[row1*32 + lane] = h1;
    }
}

// ---------------- K4: fused FFN v3 — B operands straight from L2 -------------
// 32 rows/block, 256 thr (8 warps: rg = warp>>2, nq = warp&3).
// smem: only A tile + G tile (25.6KB). 2 syncthreads per f-chunk.
__global__ __launch_bounds__(256) void k_ffn(const float* __restrict__ W1,
                                             const float* __restrict__ b1v,
                                             const float* __restrict__ W2,
                                             const float* __restrict__ b2v,
                                             float* __restrict__ out) {
    int r0 = blockIdx.x*32;
    int tid = threadIdx.x;
    int cntb = g_cnt[r0 >> 8];
    if ((r0 & (NN-1)) >= cntb) {                 // fully padded: out must be 0
        for (int t4 = tid; t4 < 32*32; t4 += 256)
            ((float4*)(out + (size_t)r0*DIM))[t4] = make_float4(0.f,0.f,0.f,0.f);
        return;
    }
    __shared__ float As[32*132];
    __shared__ float G[32*68];
    int warp = tid >> 5, lane = tid & 31;
    int g = lane >> 2, tg = lane & 3;
    int rg = warp >> 2, nq = warp & 3;
    int arow = rg*16 + g;

    // stage A (g_hn tile) once, float4 + tf32
    {
        const float4* src = (const float4*)(g_hn + (size_t)r0*DIM);
        for (int t4 = tid; t4 < 32*32; t4 += 256) {
            int r = t4 >> 5, cq = t4 & 31;
            *(float4*)(As + r*132 + cq*4) = f2tf_4(src[t4]);
        }
    }
    __syncthreads();

    float c2[4][4];
    #pragma unroll
    for (int q = 0; q < 4; q++)
        #pragma unroll
        for (int q2 = 0; q2 < 4; q2++) c2[q][q2] = 0.0f;

    for (int fc = 0; fc < 8; fc++) {
        // FF1: A from smem, B = W1 chunk straight from gmem (L2-hot)
        float cg[2][4];
        #pragma unroll
        for (int q = 0; q < 2; q++)
            #pragma unroll
            for (int q2 = 0; q2 < 4; q2++) cg[q][q2] = 0.0f;
        #pragma unroll
        for (int ks = 0; ks < 16; ks++) {
            int k0 = ks*8;
            uint32_t a0 = __float_as_uint(As[arow*132 + k0+tg]);
            uint32_t a1 = __float_as_uint(As[(arow+8)*132 + k0+tg]);
            uint32_t a2 = __float_as_uint(As[arow*132 + k0+tg+4]);
            uint32_t a3 = __float_as_uint(As[(arow+8)*132 + k0+tg+4]);
            #pragma unroll
            for (int q = 0; q < 2; q++) {
                int n = fc*64 + nq*16 + q*8 + g;
                uint32_t b0 = f2tf_u(W1[(size_t)(k0+tg)*FFD + n]);
                uint32_t b1 = f2tf_u(W1[(size_t)(k0+tg+4)*FFD + n]);
                mma8(cg[q], a0, a1, a2, a3, b0, b1);
            }
        }
        // gelu epilogue -> G (tf32); G free (prior FF2 drained by loop-end sync)
        #pragma unroll
        for (int q = 0; q < 2; q++) {
            #pragma unroll
            for (int q2 = 0; q2 < 4; q2++) {
                int row = rg*16 + g + ((q2 >= 2) ? 8 : 0);
                int cc  = nq*16 + q*8 + 2*tg + (q2 & 1);
                float xv = cg[q][q2] + b1v[fc*64 + cc];
                float u = 0.7978845608f * (xv + 0.044715f * xv * xv * xv);
                float th; asm("tanh.approx.f32 %0, %1;" : "=f"(th) : "f"(u));
                G[row*68 + cc] = f2tf_f(0.5f * xv * (1.0f + th));
            }
        }
        __syncthreads();                          // G ready for all warps
        // FF2: A from G (smem), B = W2 chunk from gmem
        #pragma unroll
        for (int ks = 0; ks < 8; ks++) {
            int k0 = ks*8;
            uint32_t a0 = __float_as_uint(G[arow*68 + k0+tg]);
            uint32_t a1 = __float_as_uint(G[(arow+8)*68 + k0+tg]);
            uint32_t a2 = __float_as_uint(G[arow*68 + k0+tg+4]);
            uint32_t a3 = __float_as_uint(G[(arow+8)*68 + k0+tg+4]);
            #pragma unroll
            for (int q = 0; q < 4; q++) {
                int n = nq*32 + q*8 + g;
                uint32_t b0 = f2tf_u(W2[(size_t)(fc*64 + k0+tg)*DIM + n]);
                uint32_t b1 = f2tf_u(W2[(size_t)(fc*64 + k0+tg+4)*DIM + n]);
                mma8(c2[q], a0, a1, a2, a3, b0, b1);
            }
        }
        __syncthreads();                          // G free for next chunk
    }

    // epilogue: + b2 + residual, mask padding
    #pragma unroll
    for (int q = 0; q < 4; q++) {
        #pragma unroll
        for (int q2 = 0; q2 < 4; q2++) {
            int rl  = rg*16 + g + ((q2 >= 2) ? 8 : 0);
            int cc  = nq*32 + q*8 + 2*tg + (q2 & 1);
            int row = r0 + rl;
            float vv = c2[q][q2] + b2v[cc] + g_h[(size_t)row*DIM + cc];
            out[(size_t)row*DIM + cc] = ((row & (NN-1)) < cntb) ? vv : 0.0f;
        }
    }
}

// ---------------- launch ----------------
extern "C" void kernel_launch(void* const* d_in, const int* in_sizes, int n_in,
                              void* d_out, int out_size) {
    const int*   x     = (const int*)  d_in[0];
    const float* pos   = (const float*)d_in[1];
    const int*   batch = (const int*)  d_in[2];
    const float* embed = (const float*)d_in[3];
    const float* Wq    = (const float*)d_in[4];
    const float* Wk    = (const float*)d_in[5];
    const float* Wv    = (const float*)d_in[6];
    const float* Wrbf  = (const float*)d_in[7];
    const float* Wo    = (const float*)d_in[8];
    const float* ln1g  = (const float*)d_in[9];
    const float* ln1b  = (const float*)d_in[10];
    const float* ln2g  = (const float*)d_in[11];
    const float* ln2b  = (const float*)d_in[12];
    const float* W1    = (const float*)d_in[13];
    const float* b1    = (const float*)d_in[14];
    const float* W2    = (const float*)d_in[15];
    const float* b2    = (const float*)d_in[16];
    float* out = (float*)d_out;

    cudaFuncSetAttribute(k_attn, cudaFuncAttributeMaxDynamicSharedMemorySize, ATTN_DYN);

    k_vocab<<<VV, DIM>>>(embed, Wq, Wk, Wv, ln1g, ln1b, batch);
    k_scatter<<<TT, 96>>>(x, pos, batch, embed);
    k_attn<<<dim3(NN/16, BB), 288, ATTN_DYN>>>(Wrbf, Wo, ln2g, ln2b);
    k_ffn<<<BN/32, 256>>>(W1, b1, W2, b2, out);   // 4th -> profiled
}

// round 16
// speedup vs baseline: 1.2226x; 1.2226x over previous
#include <cuda_runtime.h>
#include <cstdint>

#define BB   64
#define NN   256
#define TT   10240
#define VV   100
#define DIM  128
#define HH   9
#define HD   72
#define RR   8
#define FFD  512
#define BN   (BB*NN)
#define JC   32
#define UTS  40

// attention dyn smem layout (floats)
#define QS 76
#define KS 76
#define VS 76
#define ES 36
#define OS 76
#define oQ  0
#define oK  (16*QS)
#define oV  (oK + JC*KS)
#define oE  (oV + JC*VS)
#define oUT (oE + 9*16*ES)
#define oO  (oUT + 16*UTS*2)
#define ATTN_DYN ((oO + 16*OS)*4)

// ffn dyn smem layout (floats) — 32-row tiles
#define oAs 0                         // [32][132]
#define oBs (32*132)                  // W1 chunk [128][68] / W2 chunk [64][132]
#define oG  (oBs + 128*68)            // [32][68]
#define FFN_DYN ((oG + 32*68)*4)      // 60416 B -> 3 blocks/SM

// ---------------- scratch ----------------
__device__ float g_h[BN*DIM];
__device__ float g_hn[BN*DIM];
__device__ float g_q[BN*HD];
__device__ float g_k[BN*HD];
__device__ float g_v[BN*HD];
__device__ float g_coors[BN*3];
__device__ int   g_starts[BB];
__device__ int   g_cnt[BB];
__device__ float g_qt[VV*HD], g_kt[VV*HD], g_vt[VV*HD];

// 2^x; exact 0 below -120
__device__ __forceinline__ float exp2p(float x) {
    if (x < -120.0f) return 0.0f;
    float n = floorf(x);
    float t = x - n;
    float p = 1.0f + t*(0.69314718f + t*(0.24022651f + t*(0.05550411f +
              t*(0.00961812f + t*(0.00133335f + t*1.54035e-4f)))));
    return __int_as_float(((int)n + 127) << 23) * p;
}

__device__ __forceinline__ float f2tf_f(float x) {
    uint32_t r; asm("cvt.rna.tf32.f32 %0, %1;" : "=r"(r) : "f"(x));
    return __uint_as_float(r);
}
__device__ __forceinline__ float4 f2tf_4(float4 v) {
    return make_float4(f2tf_f(v.x), f2tf_f(v.y), f2tf_f(v.z), f2tf_f(v.w));
}
__device__ __forceinline__ void mma8(float* c, uint32_t a0, uint32_t a1, uint32_t a2,
                                     uint32_t a3, uint32_t b0, uint32_t b1) {
    asm volatile("mma.sync.aligned.m16n8k8.row.col.f32.tf32.tf32.f32 "
                 "{%0,%1,%2,%3},{%4,%5,%6,%7},{%8,%9},{%0,%1,%2,%3};"
                 : "+f"(c[0]), "+f"(c[1]), "+f"(c[2]), "+f"(c[3])
                 : "r"(a0), "r"(a1), "r"(a2), "r"(a3), "r"(b0), "r"(b1));
}

// ---------------- K1: per-vocab LN1 + QKV tables (+starts in block 0) --------
__global__ void k_vocab(const float* __restrict__ embed, const float* __restrict__ Wq,
                        const float* __restrict__ Wk, const float* __restrict__ Wv,
                        const float* __restrict__ g1, const float* __restrict__ b1,
                        const int* __restrict__ batch) {
    int r = blockIdx.x, t = threadIdx.x;
    if (r == 0 && t < BB) {
        int b = t;
        int lo = 0, hi = TT;
        while (lo < hi) { int mid = (lo + hi) >> 1; if (batch[mid] < b) lo = mid + 1; else hi = mid; }
        g_starts[b] = lo;
        int lo2 = 0, hi2 = TT, b1i = b + 1;
        while (lo2 < hi2) { int mid = (lo2 + hi2) >> 1; if (batch[mid] < b1i) lo2 = mid + 1; else hi2 = mid; }
        int c = lo2 - lo;
        g_cnt[b] = c > NN ? NN : c;
    }
    __shared__ float hn[DIM];
    __shared__ float2 red[4];
    float v = embed[r*DIM + t];
    float s = v, s2 = v*v;
    #pragma unroll
    for (int o = 16; o; o >>= 1) {
        s  += __shfl_xor_sync(0xffffffffu, s,  o);
        s2 += __shfl_xor_sync(0xffffffffu, s2, o);
    }
    if ((t & 31) == 0) red[t >> 5] = make_float2(s, s2);
    __syncthreads();
    float S  = red[0].x + red[1].x + red[2].x + red[3].x;
    float S2 = red[0].y + red[1].y + red[2].y + red[3].y;
    float mu  = S * (1.0f/DIM);
    float var = S2 * (1.0f/DIM) - mu*mu;
    hn[t] = (v - mu) * rsqrtf(var + 1e-5f) * g1[t] + b1[t];
    __syncthreads();
    for (int c = t; c < 3*HD; c += DIM) {
        const float* W = (c < HD) ? Wq : ((c < 2*HD) ? Wk : Wv);
        int col = c % HD;
        float a = 0.0f;
        #pragma unroll 8
        for (int d = 0; d < DIM; d++) a += hn[d] * W[d*HD + col];
        float* Tb = (c < HD) ? g_qt : ((c < 2*HD) ? g_kt : g_vt);
        Tb[r*HD + col] = a;
    }
}

// ---------------- K2: scatter (float4; 4 tokens per block) ----------------
__global__ void k_scatter(const int* __restrict__ x, const float* __restrict__ pos,
                          const int* __restrict__ batch, const float* __restrict__ embed) {
    int t = blockIdx.x*4 + (threadIdx.x / 96);
    int d = threadIdx.x % 96;
    int b = batch[t];
    int idx = t - g_starts[b];
    if (idx >= NN) return;
    int row = b*NN + idx;
    int xv = x[t];
    if (d < 32) {
        ((float4*)g_h)[(size_t)row*32 + d] = ((const float4*)embed)[(size_t)xv*32 + d];
    } else if (d < 50) {
        ((float4*)g_q)[(size_t)row*18 + (d-32)] = ((const float4*)g_qt)[xv*18 + (d-32)];
    } else if (d < 68) {
        ((float4*)g_k)[(size_t)row*18 + (d-50)] = ((const float4*)g_kt)[xv*18 + (d-50)];
    } else if (d < 86) {
        ((float4*)g_v)[(size_t)row*18 + (d-68)] = ((const float4*)g_vt)[xv*18 + (d-68)];
    } else if (d < 89) {
        g_coors[row*3 + (d-86)] = pos[t*3 + (d-86)];
    }
}

// ---------------- K3: attention + fused LN2 (R14, unchanged) ----------------
__global__ __launch_bounds__(288, 3) void k_attn(const float* __restrict__ Wrbf,
                                                 const float* __restrict__ Wo,
                                                 const float* __restrict__ ln2g,
                                                 const float* __restrict__ ln2b) {
    int b = blockIdx.y, i0 = blockIdx.x*16, tid = threadIdx.x;
    int cnt = g_cnt[b];
    if (i0 >= cnt) return;
    int nch = (cnt + JC - 1) / JC;
    int w = tid >> 5, lane = tid & 31, g = lane >> 2, tg = lane & 3;
    extern __shared__ float dyn[];
    float*  sQ  = dyn + oQ;
    float*  sK  = dyn + oK;
    float*  sV  = dyn + oV;
    float*  sE  = dyn + oE;
    float2* sUT = (float2*)(dyn + oUT);
    float*  sO  = dyn + oO;
    __shared__ __align__(16) float sW4[HH*8];
    __shared__ float sCI[48];

    {
        const float4* src = (const float4*)(g_q + (size_t)(b*NN + i0)*HD);
        for (int t4 = tid; t4 < 16*18; t4 += 288) {
            float4 vq = src[t4];
            float* dst = sQ + (t4/18)*QS + (t4%18)*4;
            dst[0]=f2tf_f(vq.x); dst[1]=f2tf_f(vq.y); dst[2]=f2tf_f(vq.z); dst[3]=f2tf_f(vq.w);
        }
    }
    if (tid < HH*8) {
        int h = tid >> 3, r = tid & 7;
        float cr = 1.14285714f * (float)r;
        sW4[h*8 + r] = Wrbf[r*HH + h] * expf(-0.5f*cr*cr);
    }
    if (tid < 48) sCI[tid] = g_coors[(b*NN + i0)*3 + tid];
    __syncthreads();

    uint32_t aq0 = __float_as_uint(sQ[g*QS + w*8 + tg]);
    uint32_t aq1 = __float_as_uint(sQ[(g+8)*QS + w*8 + tg]);
    uint32_t aq2 = __float_as_uint(sQ[g*QS + w*8 + tg + 4]);
    uint32_t aq3 = __float_as_uint(sQ[(g+8)*QS + w*8 + tg + 4]);

    float oc[4] = {0.f,0.f,0.f,0.f};
    float rs0 = 0.f, rs1 = 0.f;
    float* Eh = sE + w*16*ES;

    for (int c = 0; c < nch; c++) {
        __syncthreads();
        {
            const float4* ksrc = (const float4*)(g_k + (size_t)(b*NN + c*JC)*HD);
            const float4* vsrc = (const float4*)(g_v + (size_t)(b*NN + c*JC)*HD);
            for (int t4 = tid; t4 < JC*18; t4 += 288) {
                int r = t4/18, c4 = t4%18;
                float4 kv = ksrc[t4];
                float* kd = sK + r*KS + c4*4;
                kd[0]=f2tf_f(kv.x); kd[1]=f2tf_f(kv.y); kd[2]=f2tf_f(kv.z); kd[3]=f2tf_f(kv.w);
                float4 vv = vsrc[t4];
                float* vd = sV + r*VS + c4*4;
                vd[0]=f2tf_f(vv.x); vd[1]=f2tf_f(vv.y); vd[2]=f2tf_f(vv.z); vd[3]=f2tf_f(vv.w);
            }
        }
        for (int p = tid; p < 16*JC; p += 288) {
            int i = p >> 5, j = p & 31;
            int jj = c*JC + j;
            float2 ut;
            if (i0 + i < cnt && jj < cnt) {
                int rowj = b*NN + jj;
                float dx = sCI[i*3]  - g_coors[rowj*3];
                float dy = sCI[i*3+1]- g_coors[rowj*3+1];
                float dz = sCI[i*3+2]- g_coors[rowj*3+2];
                float ss = dx*dx + dy*dy + dz*dz + 1e-8f;
                if (ss < 200.0f) {
                    float dist = ss * rsqrtf(ss);
                    ut.x = 1.44269504f * exp2p(-0.72134752f * ss);
                    ut.y = exp2p(1.64879462f * dist);
                } else { ut.x = 0.0f; ut.y = 1.0f; }
            } else { ut.x = 0.0f; ut.y = -1.0f; }
            sUT[i*UTS + j] = ut;
        }
        __syncthreads();

        float4 w0 = *(const float4*)(sW4 + w*8);
        float4 w1 = *(const float4*)(sW4 + w*8 + 4);

        #pragma unroll
        for (int nt = 0; nt < 4; nt++) {
            float cf[4] = {0.f,0.f,0.f,0.f};
            int kro = (nt*8 + g)*KS + w*8;
            uint32_t b0 = __float_as_uint(sK[kro + tg]);
            uint32_t b1 = __float_as_uint(sK[kro + tg + 4]);
            mma8(cf, aq0, aq1, aq2, aq3, b0, b1);
            int j0 = nt*8 + 2*tg;
            #pragma unroll
            for (int q = 0; q < 4; q++) {
                int ii = (q >= 2) ? (g+8) : g;
                int jj2 = j0 + (q & 1);
                float2 ut = sUT[ii*UTS + jj2];
                float e;
                if (ut.y < 0.0f) e = 0.0f;
                else {
                    float tt = ut.y;
                    float acc = w1.w;
                    acc = acc*tt + w1.z;  acc = acc*tt + w1.y;  acc = acc*tt + w1.x;
                    acc = acc*tt + w0.w;  acc = acc*tt + w0.z;  acc = acc*tt + w0.y;
                    acc = acc*tt + w0.x;
                    e = exp2p(cf[q]*0.51012853f + acc*ut.x);
                }
                if (q < 2) rs0 += e; else rs1 += e;
                Eh[ii*ES + jj2] = f2tf_f(e);
            }
        }

        #pragma unroll
        for (int ks = 0; ks < 4; ks++) {
            uint32_t a0 = __float_as_uint(Eh[g*ES + ks*8 + tg]);
            uint32_t a1 = __float_as_uint(Eh[(g+8)*ES + ks*8 + tg]);
            uint32_t a2 = __float_as_uint(Eh[g*ES + ks*8 + tg + 4]);
            uint32_t a3 = __float_as_uint(Eh[(g+8)*ES + ks*8 + tg + 4]);
            uint32_t b0 = __float_as_uint(sV[(ks*8 + tg)*VS + w*8 + g]);
            uint32_t b1 = __float_as_uint(sV[(ks*8 + tg + 4)*VS + w*8 + g]);
            mma8(oc, a0, a1, a2, a3, b0, b1);
        }
    }

    rs0 += __shfl_xor_sync(0xffffffffu, rs0, 1);
    rs0 += __shfl_xor_sync(0xffffffffu, rs0, 2);
    rs1 += __shfl_xor_sync(0xffffffffu, rs1, 1);
    rs1 += __shfl_xor_sync(0xffffffffu, rs1, 2);
    float inv0 = (rs0 > 0.0f) ? 1.0f/rs0 : 0.0f;
    float inv1 = (rs1 > 0.0f) ? 1.0f/rs1 : 0.0f;
    sO[g*OS + w*8 + 2*tg]       = oc[0]*inv0;
    sO[g*OS + w*8 + 2*tg + 1]   = oc[1]*inv0;
    sO[(g+8)*OS + w*8 + 2*tg]   = oc[2]*inv1;
    sO[(g+8)*OS + w*8 + 2*tg+1] = oc[3]*inv1;
    __syncthreads();

    if (w < 8) {
        int r0 = 2*w, r1 = 2*w + 1;
        size_t row0 = (size_t)(b*NN + i0 + r0), row1 = row0 + 1;
        const float4* Wo4 = (const float4*)Wo;
        float4 a0 = ((const float4*)g_h)[row0*32 + lane];
        float4 a1 = ((const float4*)g_h)[row1*32 + lane];
        #pragma unroll 8
        for (int cc = 0; cc < HD; cc++) {
            float4 wv = Wo4[cc*32 + lane];
            float s0 = sO[r0*OS + cc], s1 = sO[r1*OS + cc];
            a0.x += s0*wv.x; a0.y += s0*wv.y; a0.z += s0*wv.z; a0.w += s0*wv.w;
            a1.x += s1*wv.x; a1.y += s1*wv.y; a1.z += s1*wv.z; a1.w += s1*wv.w;
        }
        float s0 = a0.x+a0.y+a0.z+a0.w, q0 = a0.x*a0.x+a0.y*a0.y+a0.z*a0.z+a0.w*a0.w;
        float s1 = a1.x+a1.y+a1.z+a1.w, q1 = a1.x*a1.x+a1.y*a1.y+a1.z*a1.z+a1.w*a1.w;
        #pragma unroll
        for (int o = 16; o; o >>= 1) {
            s0 += __shfl_xor_sync(0xffffffffu, s0, o);
            q0 += __shfl_xor_sync(0xffffffffu, q0, o);
            s1 += __shfl_xor_sync(0xffffffffu, s1, o);
            q1 += __shfl_xor_sync(0xffffffffu, q1, o);
        }
        float mu0 = s0*(1.0f/DIM), var0 = q0*(1.0f/DIM) - mu0*mu0;
        float mu1 = s1*(1.0f/DIM), var1 = q1*(1.0f/DIM) - mu1*mu1;
        float ri0 = rsqrtf(var0 + 1e-5f), ri1 = rsqrtf(var1 + 1e-5f);
        float4 gv = ((const float4*)ln2g)[lane], bv = ((const float4*)ln2b)[lane];
        float4 h0, h1;
        h0.x = (a0.x-mu0)*ri0*gv.x + bv.x;  h0.y = (a0.y-mu0)*ri0*gv.y + bv.y;
        h0.z = (a0.z-mu0)*ri0*gv.z + bv.z;  h0.w = (a0.w-mu0)*ri0*gv.w + bv.w;
        h1.x = (a1.x-mu1)*ri1*gv.x + bv.x;  h1.y = (a1.y-mu1)*ri1*gv.y + bv.y;
        h1.z = (a1.z-mu1)*ri1*gv.z + bv.z;  h1.w = (a1.w-mu1)*ri1*gv.w + bv.w;
        ((float4*)g_h)[row0*32 + lane]  = a0;
        ((float4*)g_h)[row1*32 + lane]  = a1;
        ((float4*)g_hn)[row0*32 + lane] = h0;
        ((float4*)g_hn)[row1*32 + lane] = h1;
    }
}

// ---------------- K4: fused FFN (R14 version: smem-staged W, 32-row tiles) ---
__global__ __launch_bounds__(256) void k_ffn(const float* __restrict__ W1,
                                             const float* __restrict__ b1v,
                                             const float* __restrict__ W2,
                                             const float* __restrict__ b2v,
                                             float* __restrict__ out) {
    int r0 = blockIdx.x*32;
    int tid = threadIdx.x;
    int cntb = g_cnt[r0 >> 8];
    if ((r0 & (NN-1)) >= cntb) {                 // fully padded: out must be 0
        for (int t4 = tid; t4 < 32*32; t4 += 256)
            ((float4*)(out + (size_t)r0*DIM))[t4] = make_float4(0.f,0.f,0.f,0.f);
        return;
    }
    extern __shared__ float fdyn[];
    float* As  = fdyn + oAs;    // [32][132]
    float* Bs  = fdyn + oBs;    // W1 [128][68] / W2 [64][132]
    float* G   = fdyn + oG;     // [32][68]
    int warp = tid >> 5, lane = tid & 31;
    int g = lane >> 2, tg = lane & 3;
    int rg = warp >> 2, nq = warp & 3;
    int arow = rg*16 + g;

    // stage A (g_hn tile) once, float4 + tf32
    {
        const float4* src = (const float4*)(g_hn + (size_t)r0*DIM);
        for (int t4 = tid; t4 < 32*32; t4 += 256) {
            int r = t4 >> 5, cq = t4 & 31;
            *(float4*)(As + r*132 + cq*4) = f2tf_4(src[t4]);
        }
    }

    float c2[4][4];
    #pragma unroll
    for (int q = 0; q < 4; q++)
        #pragma unroll
        for (int q2 = 0; q2 < 4; q2++) c2[q][q2] = 0.0f;

    for (int fc = 0; fc < 8; fc++) {
        __syncthreads();                          // Bs/G free; As ready (fc=0)
        // stage W1 chunk [128 k][64 n], float4
        {
            const float4* src = (const float4*)(W1 + fc*64);
            for (int t4 = tid; t4 < 128*16; t4 += 256) {
                int k = t4 >> 4, cq = t4 & 15;
                *(float4*)(Bs + k*68 + cq*4) = f2tf_4(src[k*(FFD/4) + cq]);
            }
        }
        __syncthreads();
        // FF1: warp (rg, nq) -> G rows rg*16..+15, f-cols nq*16..+15
        float cg[2][4];
        #pragma unroll
        for (int q = 0; q < 2; q++)
            #pragma unroll
            for (int q2 = 0; q2 < 4; q2++) cg[q][q2] = 0.0f;
        #pragma unroll
        for (int ks = 0; ks < 16; ks++) {
            int k0 = ks*8;
            uint32_t a0 = __float_as_uint(As[arow*132 + k0+tg]);
            uint32_t a1 = __float_as_uint(As[(arow+8)*132 + k0+tg]);
            uint32_t a2 = __float_as_uint(As[arow*132 + k0+tg+4]);
            uint32_t a3 = __float_as_uint(As[(arow+8)*132 + k0+tg+4]);
            #pragma unroll
            for (int q = 0; q < 2; q++) {
                int n = nq*16 + q*8 + g;
                uint32_t b0 = __float_as_uint(Bs[(k0+tg)*68 + n]);
                uint32_t b1 = __float_as_uint(Bs[(k0+tg+4)*68 + n]);
                mma8(cg[q], a0, a1, a2, a3, b0, b1);
            }
        }
        // gelu epilogue -> G (tf32)
        #pragma unroll
        for (int q = 0; q < 2; q++) {
            #pragma unroll
            for (int q2 = 0; q2 < 4; q2++) {
                int row = rg*16 + g + ((q2 >= 2) ? 8 : 0);
                int cc  = nq*16 + q*8 + 2*tg + (q2 & 1);
                float xv = cg[q][q2] + b1v[fc*64 + cc];
                float u = 0.7978845608f * (xv + 0.044715f * xv * xv * xv);
                float th; asm("tanh.approx.f32 %0, %1;" : "=f"(th) : "f"(u));
                G[row*68 + cc] = f2tf_f(0.5f * xv * (1.0f + th));
            }
        }
        __syncthreads();                          // G complete, Bs (W1) consumed
        // stage W2 chunk [64 k][128 n], float4
        {
            const float4* src = (const float4*)(W2 + (size_t)fc*64*DIM);
            for (int t4 = tid; t4 < 64*32; t4 += 256) {
                int k = t4 >> 5, cq = t4 & 31;
                *(float4*)(Bs + k*132 + cq*4) = f2tf_4(src[k*32 + cq]);
            }
        }
        __syncthreads();                          // Bs (W2) + G visible
        // FF2: warp (rg, nq): rows rg*16..+15, d-cols nq*32..+31
        #pragma unroll
        for (int ks = 0; ks < 8; ks++) {
            int k0 = ks*8;
            uint32_t a0 = __float_as_uint(G[arow*68 + k0+tg]);
            uint32_t a1 = __float_as_uint(G[(arow+8)*68 + k0+tg]);
            uint32_t a2 = __float_as_uint(G[arow*68 + k0+tg+4]);
            uint32_t a3 = __float_as_uint(G[(arow+8)*68 + k0+tg+4]);
            #pragma unroll
            for (int q = 0; q < 4; q++) {
                int n = nq*32 + q*8 + g;
                uint32_t b0 = __float_as_uint(Bs[(k0+tg)*132 + n]);
                uint32_t b1 = __float_as_uint(Bs[(k0+tg+4)*132 + n]);
                mma8(c2[q], a0, a1, a2, a3, b0, b1);
            }
        }
    }

    // epilogue: + b2 + residual, mask padding
    #pragma unroll
    for (int q = 0; q < 4; q++) {
        #pragma unroll
        for (int q2 = 0; q2 < 4; q2++) {
            int rl  = rg*16 + g + ((q2 >= 2) ? 8 : 0);
            int cc  = nq*32 + q*8 + 2*tg + (q2 & 1);
            int row = r0 + rl;
            float vv = c2[q][q2] + b2v[cc] + g_h[(size_t)row*DIM + cc];
            out[(size_t)row*DIM + cc] = ((row & (NN-1)) < cntb) ? vv : 0.0f;
        }
    }
}

// ---------------- launch ----------------
extern "C" void kernel_launch(void* const* d_in, const int* in_sizes, int n_in,
                              void* d_out, int out_size) {
    const int*   x     = (const int*)  d_in[0];
    const float* pos   = (const float*)d_in[1];
    const int*   batch = (const int*)  d_in[2];
    const float* embed = (const float*)d_in[3];
    const float* Wq    = (const float*)d_in[4];
    const float* Wk    = (const float*)d_in[5];
    const float* Wv    = (const float*)d_in[6];
    const float* Wrbf  = (const float*)d_in[7];
    const float* Wo    = (const float*)d_in[8];
    const float* ln1g  = (const float*)d_in[9];
    const float* ln1b  = (const float*)d_in[10];
    const float* ln2g  = (const float*)d_in[11];
    const float* ln2b  = (const float*)d_in[12];
    const float* W1    = (const float*)d_in[13];
    const float* b1    = (const float*)d_in[14];
    const float* W2    = (const float*)d_in[15];
    const float* b2    = (const float*)d_in[16];
    float* out = (float*)d_out;

    cudaFuncSetAttribute(k_attn, cudaFuncAttributeMaxDynamicSharedMemorySize, ATTN_DYN);
    cudaFuncSetAttribute(k_ffn,  cudaFuncAttributeMaxDynamicSharedMemorySize, FFN_DYN);

    k_vocab<<<VV, DIM>>>(embed, Wq, Wk, Wv, ln1g, ln1b, batch);
    k_scatter<<<TT/4, 384>>>(x, pos, batch, embed);
    k_attn<<<dim3(NN/16, BB), 288, ATTN_DYN>>>(Wrbf, Wo, ln2g, ln2b);
    k_ffn<<<BN/32, 256, FFN_DYN>>>(W1, b1, W2, b2, out);   // 4th -> profiled
}

// round 17
// speedup vs baseline: 1.3344x; 1.0915x over previous
#include <cuda_runtime.h>
#include <cstdint>

#define BB   64
#define NN   256
#define TT   10240
#define VV   100
#define DIM  128
#define HH   9
#define HD   72
#define RR   8
#define FFD  512
#define BN   (BB*NN)
#define JC   32
#define UTS  40

// attention dyn smem layout (floats)
#define QS 76              // g-row pattern: stride ≡ 4 (mod 32) conflict-free
#define KS 76              // g-row pattern
#define VS 72              // tg-row pattern: stride ≡ 8 (mod 32) conflict-free
#define ES 36
#define OS 76
#define oQ  0
#define oK  (16*QS)                  // 1216
#define oV  (oK + JC*KS)             // 3648
#define oE  (oV + JC*VS)             // 5952
#define oUT (oE + 9*16*ES)           // 11136
#define oO  (oUT + 16*UTS*2)         // 12416
#define ATTN_DYN ((oO + 16*OS)*4)    // 54528 B

// ffn dyn smem layout (floats) — 32-row tiles, conflict-free B strides
#define BS1 72             // W1 chunk row stride (tg-row pattern: ≡8 mod 32)
#define BS2 136            // W2 chunk row stride (tg-row pattern: ≡8 mod 32)
#define oAs 0                         // [32][132]  (g-row: 132 ≡ 4 ✓)
#define oBs (32*132)                  // 4224; Bs = max(128*72, 64*136) = 9216
#define oG  (oBs + 128*BS1)           // 13440; G [32][68] (g-row: 68 ≡ 4 ✓)
#define FFN_DYN ((oG + 32*68)*4)      // 62464 B -> 3 blocks/SM

// ---------------- scratch ----------------
__device__ float g_h[BN*DIM];
__device__ float g_hn[BN*DIM];
__device__ float g_q[BN*HD];
__device__ float g_k[BN*HD];
__device__ float g_v[BN*HD];
__device__ float g_coors[BN*3];
__device__ int   g_starts[BB];
__device__ int   g_cnt[BB];
__device__ float g_qt[VV*HD], g_kt[VV*HD], g_vt[VV*HD];

// 2^x; exact 0 below -120
__device__ __forceinline__ float exp2p(float x) {
    if (x < -120.0f) return 0.0f;
    float n = floorf(x);
    float t = x - n;
    float p = 1.0f + t*(0.69314718f + t*(0.24022651f + t*(0.05550411f +
              t*(0.00961812f + t*(0.00133335f + t*1.54035e-4f)))));
    return __int_as_float(((int)n + 127) << 23) * p;
}

__device__ __forceinline__ float f2tf_f(float x) {
    uint32_t r; asm("cvt.rna.tf32.f32 %0, %1;" : "=r"(r) : "f"(x));
    return __uint_as_float(r);
}
__device__ __forceinline__ float4 f2tf_4(float4 v) {
    return make_float4(f2tf_f(v.x), f2tf_f(v.y), f2tf_f(v.z), f2tf_f(v.w));
}
__device__ __forceinline__ void mma8(float* c, uint32_t a0, uint32_t a1, uint32_t a2,
                                     uint32_t a3, uint32_t b0, uint32_t b1) {
    asm volatile("mma.sync.aligned.m16n8k8.row.col.f32.tf32.tf32.f32 "
                 "{%0,%1,%2,%3},{%4,%5,%6,%7},{%8,%9},{%0,%1,%2,%3};"
                 : "+f"(c[0]), "+f"(c[1]), "+f"(c[2]), "+f"(c[3])
                 : "r"(a0), "r"(a1), "r"(a2), "r"(a3), "r"(b0), "r"(b1));
}

// ---------------- K1: per-vocab LN1 + QKV tables (+starts in block 0) --------
__global__ void k_vocab(const float* __restrict__ embed, const float* __restrict__ Wq,
                        const float* __restrict__ Wk, const float* __restrict__ Wv,
                        const float* __restrict__ g1, const float* __restrict__ b1,
                        const int* __restrict__ batch) {
    int r = blockIdx.x, t = threadIdx.x;
    if (r == 0 && t < BB) {
        int b = t;
        int lo = 0, hi = TT;
        while (lo < hi) { int mid = (lo + hi) >> 1; if (batch[mid] < b) lo = mid + 1; else hi = mid; }
        g_starts[b] = lo;
        int lo2 = 0, hi2 = TT, b1i = b + 1;
        while (lo2 < hi2) { int mid = (lo2 + hi2) >> 1; if (batch[mid] < b1i) lo2 = mid + 1; else hi2 = mid; }
        int c = lo2 - lo;
        g_cnt[b] = c > NN ? NN : c;
    }
    __shared__ float hn[DIM];
    __shared__ float2 red[4];
    float v = embed[r*DIM + t];
    float s = v, s2 = v*v;
    #pragma unroll
    for (int o = 16; o; o >>= 1) {
        s  += __shfl_xor_sync(0xffffffffu, s,  o);
        s2 += __shfl_xor_sync(0xffffffffu, s2, o);
    }
    if ((t & 31) == 0) red[t >> 5] = make_float2(s, s2);
    __syncthreads();
    float S  = red[0].x + red[1].x + red[2].x + red[3].x;
    float S2 = red[0].y + red[1].y + red[2].y + red[3].y;
    float mu  = S * (1.0f/DIM);
    float var = S2 * (1.0f/DIM) - mu*mu;
    hn[t] = (v - mu) * rsqrtf(var + 1e-5f) * g1[t] + b1[t];
    __syncthreads();
    for (int c = t; c < 3*HD; c += DIM) {
        const float* W = (c < HD) ? Wq : ((c < 2*HD) ? Wk : Wv);
        int col = c % HD;
        float a = 0.0f;
        #pragma unroll 8
        for (int d = 0; d < DIM; d++) a += hn[d] * W[d*HD + col];
        float* Tb = (c < HD) ? g_qt : ((c < 2*HD) ? g_kt : g_vt);
        Tb[r*HD + col] = a;
    }
}

// ---------------- K2: scatter (float4; 4 tokens per block) ----------------
__global__ void k_scatter(const int* __restrict__ x, const float* __restrict__ pos,
                          const int* __restrict__ batch, const float* __restrict__ embed) {
    int t = blockIdx.x*4 + (threadIdx.x / 96);
    int d = threadIdx.x % 96;
    int b = batch[t];
    int idx = t - g_starts[b];
    if (idx >= NN) return;
    int row = b*NN + idx;
    int xv = x[t];
    if (d < 32) {
        ((float4*)g_h)[(size_t)row*32 + d] = ((const float4*)embed)[(size_t)xv*32 + d];
    } else if (d < 50) {
        ((float4*)g_q)[(size_t)row*18 + (d-32)] = ((const float4*)g_qt)[xv*18 + (d-32)];
    } else if (d < 68) {
        ((float4*)g_k)[(size_t)row*18 + (d-50)] = ((const float4*)g_kt)[xv*18 + (d-50)];
    } else if (d < 86) {
        ((float4*)g_v)[(size_t)row*18 + (d-68)] = ((const float4*)g_vt)[xv*18 + (d-68)];
    } else if (d < 89) {
        g_coors[row*3 + (d-86)] = pos[t*3 + (d-86)];
    }
}

// ---------------- K3: attention + fused LN2 (VS 76->72, otherwise R14) -------
__global__ __launch_bounds__(288, 3) void k_attn(const float* __restrict__ Wrbf,
                                                 const float* __restrict__ Wo,
                                                 const float* __restrict__ ln2g,
                                                 const float* __restrict__ ln2b) {
    int b = blockIdx.y, i0 = blockIdx.x*16, tid = threadIdx.x;
    int cnt = g_cnt[b];
    if (i0 >= cnt) return;
    int nch = (cnt + JC - 1) / JC;
    int w = tid >> 5, lane = tid & 31, g = lane >> 2, tg = lane & 3;
    extern __shared__ float dyn[];
    float*  sQ  = dyn + oQ;
    float*  sK  = dyn + oK;
    float*  sV  = dyn + oV;
    float*  sE  = dyn + oE;
    float2* sUT = (float2*)(dyn + oUT);
    float*  sO  = dyn + oO;
    __shared__ __align__(16) float sW4[HH*8];
    __shared__ float sCI[48];

    {
        const float4* src = (const float4*)(g_q + (size_t)(b*NN + i0)*HD);
        for (int t4 = tid; t4 < 16*18; t4 += 288) {
            float4 vq = src[t4];
            float* dst = sQ + (t4/18)*QS + (t4%18)*4;
            dst[0]=f2tf_f(vq.x); dst[1]=f2tf_f(vq.y); dst[2]=f2tf_f(vq.z); dst[3]=f2tf_f(vq.w);
        }
    }
    if (tid < HH*8) {
        int h = tid >> 3, r = tid & 7;
        float cr = 1.14285714f * (float)r;
        sW4[h*8 + r] = Wrbf[r*HH + h] * expf(-0.5f*cr*cr);
    }
    if (tid < 48) sCI[tid] = g_coors[(b*NN + i0)*3 + tid];
    __syncthreads();

    uint32_t aq0 = __float_as_uint(sQ[g*QS + w*8 + tg]);
    uint32_t aq1 = __float_as_uint(sQ[(g+8)*QS + w*8 + tg]);
    uint32_t aq2 = __float_as_uint(sQ[g*QS + w*8 + tg + 4]);
    uint32_t aq3 = __float_as_uint(sQ[(g+8)*QS + w*8 + tg + 4]);

    float oc[4] = {0.f,0.f,0.f,0.f};
    float rs0 = 0.f, rs1 = 0.f;
    float* Eh = sE + w*16*ES;

    for (int c = 0; c < nch; c++) {
        __syncthreads();
        {
            const float4* ksrc = (const float4*)(g_k + (size_t)(b*NN + c*JC)*HD);
            const float4* vsrc = (const float4*)(g_v + (size_t)(b*NN + c*JC)*HD);
            for (int t4 = tid; t4 < JC*18; t4 += 288) {
                int r = t4/18, c4 = t4%18;
                float4 kv = ksrc[t4];
                float* kd = sK + r*KS + c4*4;
                kd[0]=f2tf_f(kv.x); kd[1]=f2tf_f(kv.y); kd[2]=f2tf_f(kv.z); kd[3]=f2tf_f(kv.w);
                float4 vv = vsrc[t4];
                float* vd = sV + r*VS + c4*4;
                vd[0]=f2tf_f(vv.x); vd[1]=f2tf_f(vv.y); vd[2]=f2tf_f(vv.z); vd[3]=f2tf_f(vv.w);
            }
        }
        for (int p = tid; p < 16*JC; p += 288) {
            int i = p >> 5, j = p & 31;
            int jj = c*JC + j;
            float2 ut;
            if (i0 + i < cnt && jj < cnt) {
                int rowj = b*NN + jj;
                float dx = sCI[i*3]  - g_coors[rowj*3];
                float dy = sCI[i*3+1]- g_coors[rowj*3+1];
                float dz = sCI[i*3+2]- g_coors[rowj*3+2];
                float ss = dx*dx + dy*dy + dz*dz + 1e-8f;
                if (ss < 200.0f) {
                    float dist = ss * rsqrtf(ss);
                    ut.x = 1.44269504f * exp2p(-0.72134752f * ss);
                    ut.y = exp2p(1.64879462f * dist);
                } else { ut.x = 0.0f; ut.y = 1.0f; }
            } else { ut.x = 0.0f; ut.y = -1.0f; }
            sUT[i*UTS + j] = ut;
        }
        __syncthreads();

        float4 w0 = *(const float4*)(sW4 + w*8);
        float4 w1 = *(const float4*)(sW4 + w*8 + 4);

        #pragma unroll
        for (int nt = 0; nt < 4; nt++) {
            float cf[4] = {0.f,0.f,0.f,0.f};
            int kro = (nt*8 + g)*KS + w*8;
            uint32_t b0 = __float_as_uint(sK[kro + tg]);
            uint32_t b1 = __float_as_uint(sK[kro + tg + 4]);
            mma8(cf, aq0, aq1, aq2, aq3, b0, b1);
            int j0 = nt*8 + 2*tg;
            #pragma unroll
            for (int q = 0; q < 4; q++) {
                int ii = (q >= 2) ? (g+8) : g;
                int jj2 = j0 + (q & 1);
                float2 ut = sUT[ii*UTS + jj2];
                float e;
                if (ut.y < 0.0f) e = 0.0f;
                else {
                    float tt = ut.y;
                    float acc = w1.w;
                    acc = acc*tt + w1.z;  acc = acc*tt + w1.y;  acc = acc*tt + w1.x;
                    acc = acc*tt + w0.w;  acc = acc*tt + w0.z;  acc = acc*tt + w0.y;
                    acc = acc*tt + w0.x;
                    e = exp2p(cf[q]*0.51012853f + acc*ut.x);
                }
                if (q < 2) rs0 += e; else rs1 += e;
                Eh[ii*ES + jj2] = f2tf_f(e);
            }
        }

        #pragma unroll
        for (int ks = 0; ks < 4; ks++) {
            uint32_t a0 = __float_as_uint(Eh[g*ES + ks*8 + tg]);
            uint32_t a1 = __float_as_uint(Eh[(g+8)*ES + ks*8 + tg]);
            uint32_t a2 = __float_as_uint(Eh[g*ES + ks*8 + tg + 4]);
            uint32_t a3 = __float_as_uint(Eh[(g+8)*ES + ks*8 + tg + 4]);
            uint32_t b0 = __float_as_uint(sV[(ks*8 + tg)*VS + w*8 + g]);
            uint32_t b1 = __float_as_uint(sV[(ks*8 + tg + 4)*VS + w*8 + g]);
            mma8(oc, a0, a1, a2, a3, b0, b1);
        }
    }

    rs0 += __shfl_xor_sync(0xffffffffu, rs0, 1);
    rs0 += __shfl_xor_sync(0xffffffffu, rs0, 2);
    rs1 += __shfl_xor_sync(0xffffffffu, rs1, 1);
    rs1 += __shfl_xor_sync(0xffffffffu, rs1, 2);
    float inv0 = (rs0 > 0.0f) ? 1.0f/rs0 : 0.0f;
    float inv1 = (rs1 > 0.0f) ? 1.0f/rs1 : 0.0f;
    sO[g*OS + w*8 + 2*tg]       = oc[0]*inv0;
    sO[g*OS + w*8 + 2*tg + 1]   = oc[1]*inv0;
    sO[(g+8)*OS + w*8 + 2*tg]   = oc[2]*inv1;
    sO[(g+8)*OS + w*8 + 2*tg+1] = oc[3]*inv1;
    __syncthreads();

    if (w < 8) {
        int r0 = 2*w, r1 = 2*w + 1;
        size_t row0 = (size_t)(b*NN + i0 + r0), row1 = row0 + 1;
        const float4* Wo4 = (const float4*)Wo;
        float4 a0 = ((const float4*)g_h)[row0*32 + lane];
        float4 a1 = ((const float4*)g_h)[row1*32 + lane];
        #pragma unroll 8
        for (int cc = 0; cc < HD; cc++) {
            float4 wv = Wo4[cc*32 + lane];
            float s0 = sO[r0*OS + cc], s1 = sO[r1*OS + cc];
            a0.x += s0*wv.x; a0.y += s0*wv.y; a0.z += s0*wv.z; a0.w += s0*wv.w;
            a1.x += s1*wv.x; a1.y += s1*wv.y; a1.z += s1*wv.z; a1.w += s1*wv.w;
        }
        float s0 = a0.x+a0.y+a0.z+a0.w, q0 = a0.x*a0.x+a0.y*a0.y+a0.z*a0.z+a0.w*a0.w;
        float s1 = a1.x+a1.y+a1.z+a1.w, q1 = a1.x*a1.x+a1.y*a1.y+a1.z*a1.z+a1.w*a1.w;
        #pragma unroll
        for (int o = 16; o; o >>= 1) {
            s0 += __shfl_xor_sync(0xffffffffu, s0, o);
            q0 += __shfl_xor_sync(0xffffffffu, q0, o);
            s1 += __shfl_xor_sync(0xffffffffu, s1, o);
            q1 += __shfl_xor_sync(0xffffffffu, q1, o);
        }
        float mu0 = s0*(1.0f/DIM), var0 = q0*(1.0f/DIM) - mu0*mu0;
        float mu1 = s1*(1.0f/DIM), var1 = q1*(1.0f/DIM) - mu1*mu1;
        float ri0 = rsqrtf(var0 + 1e-5f), ri1 = rsqrtf(var1 + 1e-5f);
        float4 gv = ((const float4*)ln2g)[lane], bv = ((const float4*)ln2b)[lane];
        float4 h0, h1;
        h0.x = (a0.x-mu0)*ri0*gv.x + bv.x;  h0.y = (a0.y-mu0)*ri0*gv.y + bv.y;
        h0.z = (a0.z-mu0)*ri0*gv.z + bv.z;  h0.w = (a0.w-mu0)*ri0*gv.w + bv.w;
        h1.x = (a1.x-mu1)*ri1*gv.x + bv.x;  h1.y = (a1.y-mu1)*ri1*gv.y + bv.y;
        h1.z = (a1.z-mu1)*ri1*gv.z + bv.z;  h1.w = (a1.w-mu1)*ri1*gv.w + bv.w;
        ((float4*)g_h)[row0*32 + lane]  = a0;
        ((float4*)g_h)[row1*32 + lane]  = a1;
        ((float4*)g_hn)[row0*32 + lane] = h0;
        ((float4*)g_hn)[row1*32 + lane] = h1;
    }
}

// ---------------- K4: fused FFN (R14 + conflict-free B strides) --------------
__global__ __launch_bounds__(256) void k_ffn(const float* __restrict__ W1,
                                             const float* __restrict__ b1v,
                                             const float* __restrict__ W2,
                                             const float* __restrict__ b2v,
                                             float* __restrict__ out) {
    int r0 = blockIdx.x*32;
    int tid = threadIdx.x;
    int cntb = g_cnt[r0 >> 8];
    if ((r0 & (NN-1)) >= cntb) {                 // fully padded: out must be 0
        for (int t4 = tid; t4 < 32*32; t4 += 256)
            ((float4*)(out + (size_t)r0*DIM))[t4] = make_float4(0.f,0.f,0.f,0.f);
        return;
    }
    extern __shared__ float fdyn[];
    float* As  = fdyn + oAs;    // [32][132]
    float* Bs  = fdyn + oBs;    // W1 [128][BS1] / W2 [64][BS2]
    float* G   = fdyn + oG;     // [32][68]
    int warp = tid >> 5, lane = tid & 31;
    int g = lane >> 2, tg = lane & 3;
    int rg = warp >> 2, nq = warp & 3;
    int arow = rg*16 + g;

    // stage A (g_hn tile) once, float4 + tf32
    {
        const float4* src = (const float4*)(g_hn + (size_t)r0*DIM);
        for (int t4 = tid; t4 < 32*32; t4 += 256) {
            int r = t4 >> 5, cq = t4 & 31;
            *(float4*)(As + r*132 + cq*4) = f2tf_4(src[t4]);
        }
    }

    float c2[4][4];
    #pragma unroll
    for (int q = 0; q < 4; q++)
        #pragma unroll
        for (int q2 = 0; q2 < 4; q2++) c2[q][q2] = 0.0f;

    for (int fc = 0; fc < 8; fc++) {
        __syncthreads();                          // Bs/G free; As ready (fc=0)
        // stage W1 chunk [128 k][64 n], float4, stride BS1
        {
            const float4* src = (const float4*)(W1 + fc*64);
            for (int t4 = tid; t4 < 128*16; t4 += 256) {
                int k = t4 >> 4, cq = t4 & 15;
                *(float4*)(Bs + k*BS1 + cq*4) = f2tf_4(src[k*(FFD/4) + cq]);
            }
        }
        __syncthreads();
        // FF1: warp (rg, nq) -> G rows rg*16..+15, f-cols nq*16..+15
        float cg[2][4];
        #pragma unroll
        for (int q = 0; q < 2; q++)
            #pragma unroll
            for (int q2 = 0; q2 < 4; q2++) cg[q][q2] = 0.0f;
        #pragma unroll
        for (int ks = 0; ks < 16; ks++) {
            int k0 = ks*8;
            uint32_t a0 = __float_as_uint(As[arow*132 + k0+tg]);
            uint32_t a1 = __float_as_uint(As[(arow+8)*132 + k0+tg]);
            uint32_t a2 = __float_as_uint(As[arow*132 + k0+tg+4]);
            uint32_t a3 = __float_as_uint(As[(arow+8)*132 + k0+tg+4]);
            #pragma unroll
            for (int q = 0; q < 2; q++) {
                int n = nq*16 + q*8 + g;
                uint32_t b0 = __float_as_uint(Bs[(k0+tg)*BS1 + n]);
                uint32_t b1 = __float_as_uint(Bs[(k0+tg+4)*BS1 + n]);
                mma8(cg[q], a0, a1, a2, a3, b0, b1);
            }
        }
        // gelu epilogue -> G (tf32)
        #pragma unroll
        for (int q = 0; q < 2; q++) {
            #pragma unroll
            for (int q2 = 0; q2 < 4; q2++) {
                int row = rg*16 + g + ((q2 >= 2) ? 8 : 0);
                int cc  = nq*16 + q*8 + 2*tg + (q2 & 1);
                float xv = cg[q][q2] + b1v[fc*64 + cc];
                float u = 0.7978845608f * (xv + 0.044715f * xv * xv * xv);
                float th; asm("tanh.approx.f32 %0, %1;" : "=f"(th) : "f"(u));
                G[row*68 + cc] = f2tf_f(0.5f * xv * (1.0f + th));
            }
        }
        __syncthreads();                          // G complete, Bs (W1) consumed
        // stage W2 chunk [64 k][128 n], float4, stride BS2
        {
            const float4* src = (const float4*)(W2 + (size_t)fc*64*DIM);
            for (int t4 = tid; t4 < 64*32; t4 += 256) {
                int k = t4 >> 5, cq = t4 & 31;
                *(float4*)(Bs + k*BS2 + cq*4) = f2tf_4(src[k*32 + cq]);
            }
        }
        __syncthreads();                          // Bs (W2) + G visible
        // FF2: warp (rg, nq): rows rg*16..+15, d-cols nq*32..+31
        #pragma unroll
        for (int ks = 0; ks < 8; ks++) {
            int k0 = ks*8;
            uint32_t a0 = __float_as_uint(G[arow*68 + k0+tg]);
            uint32_t a1 = __float_as_uint(G[(arow+8)*68 + k0+tg]);
            uint32_t a2 = __float_as_uint(G[arow*68 + k0+tg+4]);
            uint32_t a3 = __float_as_uint(G[(arow+8)*68 + k0+tg+4]);
            #pragma unroll
            for (int q = 0; q < 4; q++) {
                int n = nq*32 + q*8 + g;
                uint32_t b0 = __float_as_uint(Bs[(k0+tg)*BS2 + n]);
                uint32_t b1 = __float_as_uint(Bs[(k0+tg+4)*BS2 + n]);
                mma8(c2[q], a0, a1, a2, a3, b0, b1);
            }
        }
    }

    // epilogue: + b2 + residual, mask padding
    #pragma unroll
    for (int q = 0; q < 4; q++) {
        #pragma unroll
        for (int q2 = 0; q2 < 4; q2++) {
            int rl  = rg*16 + g + ((q2 >= 2) ? 8 : 0);
            int cc  = nq*32 + q*8 + 2*tg + (q2 & 1);
            int row = r0 + rl;
            float vv = c2[q][q2] + b2v[cc] + g_h[(size_t)row*DIM + cc];
            out[(size_t)row*DIM + cc] = ((row & (NN-1)) < cntb) ? vv : 0.0f;
        }
    }
}

// ---------------- launch ----------------
extern "C" void kernel_launch(void* const* d_in, const int* in_sizes, int n_in,
                              void* d_out, int out_size) {
    const int*   x     = (const int*)  d_in[0];
    const float* pos   = (const float*)d_in[1];
    const int*   batch = (const int*)  d_in[2];
    const float* embed = (const float*)d_in[3];
    const float* Wq    = (const float*)d_in[4];
    const float* Wk    = (const float*)d_in[5];
    const float* Wv    = (const float*)d_in[6];
    const float* Wrbf  = (const float*)d_in[7];
    const float* Wo    = (const float*)d_in[8];
    const float* ln1g  = (const float*)d_in[9];
    const float* ln1b  = (const float*)d_in[10];
    const float* ln2g  = (const float*)d_in[11];
    const float* ln2b  = (const float*)d_in[12];
    const float* W1    = (const float*)d_in[13];
    const float* b1    = (const float*)d_in[14];
    const float* W2    = (const float*)d_in[15];
    const float* b2    = (const float*)d_in[16];
    float* out = (float*)d_out;

    cudaFuncSetAttribute(k_attn, cudaFuncAttributeMaxDynamicSharedMemorySize, ATTN_DYN);
    cudaFuncSetAttribute(k_ffn,  cudaFuncAttributeMaxDynamicSharedMemorySize, FFN_DYN);

    k_vocab<<<VV, DIM>>>(embed, Wq, Wk, Wv, ln1g, ln1b, batch);
    k_scatter<<<TT/4, 384>>>(x, pos, batch, embed);
    k_attn<<<dim3(NN/16, BB), 288, ATTN_DYN>>>(Wrbf, Wo, ln2g, ln2b);
    k_ffn<<<BN/32, 256, FFN_DYN>>>(W1, b1, W2, b2, out);   // 4th -> profiled
}